// round 1
// baseline (speedup 1.0000x reference)
#include <cuda_runtime.h>
#include <math.h>

// Problem constants (fixed by setup_inputs)
#define B_  8
#define T_  4096
#define D_  1024
#define A_  32
#define S_  16
#define H_  256          // max(ttl*4, S*4) = 256
#define W_  (H_ - S_ + 1)  // 241
#define NT  256          // threads per block
#define NPAIR (B_ * A_)  // 256

__device__ __forceinline__ unsigned long long compat_mask_of(int r) {
    switch (r) {
        case 11: return (1ull<<11)|(1ull<<13)|(1ull<<16);
        case 21: return (1ull<<14)|(1ull<<15)|(1ull<<21)|(1ull<<22)|(1ull<<23);
        case 31: return (1ull<<15)|(1ull<<31)|(1ull<<32)|(1ull<<33);
        case 41: return (1ull<<41)|(1ull<<42)|(1ull<<43)|(1ull<<44);
        case 51: return (1ull<<15)|(1ull<<51)|(1ull<<52)|(1ull<<53);
        default: return 0ull;
    }
}

__constant__ signed char c_alias[64] = {
    -1,-1,-1,-1,-1,-1,-1,-1,-1,-1,          // 0-9
    -1,11,-1,11,-1,-1,11,-1,-1,-1,          // 10-19
    -1,21,21,21,-1,-1,-1,-1,-1,-1,          // 20-29
    -1,31,31,31,-1,-1,-1,-1,-1,-1,          // 30-39
    -1,41,41,41,41,-1,-1,-1,-1,-1,          // 40-49
    -1,51,51,53==53?51:51,-1,-1,-1,-1,-1,-1,// 50-59 (51,52,53 -> 51)
    -1,-1,-1,-1                             // 60-63
};

__device__ __forceinline__ float blockReduceSum(float v, float* s_red, int tid) {
    s_red[tid] = v; __syncthreads();
    #pragma unroll
    for (int o = NT/2; o > 0; o >>= 1) {
        if (tid < o) s_red[tid] += s_red[tid + o];
        __syncthreads();
    }
    float r = s_red[0]; __syncthreads();
    return r;
}

__device__ __forceinline__ float blockReduceMax(float v, float* s_red, int tid) {
    s_red[tid] = v; __syncthreads();
    #pragma unroll
    for (int o = NT/2; o > 0; o >>= 1) {
        if (tid < o) s_red[tid] = fmaxf(s_red[tid], s_red[tid + o]);
        __syncthreads();
    }
    float r = s_red[0]; __syncthreads();
    return r;
}

__global__ __launch_bounds__(NT, 2)
void cm_kernel(const float* __restrict__ hidden,
               const float* __restrict__ anchor_repr,
               const int*   __restrict__ input_ids,
               const int*   __restrict__ anchor_end,
               float*       __restrict__ out)
{
    __shared__ float s_anchor[D_];
    __shared__ float s_meanf[D_];
    __shared__ float s_red[NT];
    __shared__ int   s_ftok[H_];
    __shared__ int   s_span[S_];
    __shared__ int   s_alias[64];
    __shared__ float s_shift;
    __shared__ int   s_root, s_has, s_ffmask;
    __shared__ float s_invdenom;

    const int pair = blockIdx.x;
    const int b = pair / A_;
    const int a = pair % A_;
    const int tid = threadIdx.x;
    const int lane = tid & 31;
    const int warp = tid >> 5;

    const int aend  = anchor_end[b * A_ + a];
    const int start = aend + 1;

    // ---- init smem ----
    const float* anch = anchor_repr + ((size_t)(b * A_ + a)) * D_;
    for (int i = tid; i < D_; i += NT) {
        s_anchor[i] = anch[i];
        s_meanf[i]  = 0.0f;
    }
    if (tid < 64) s_alias[tid] = (int)c_alias[tid];
    if (tid < H_) s_ftok[tid] = input_ids[b * T_ + start + tid];
    if (tid < S_) s_span[tid] = input_ids[b * T_ + aend - S_ + 1 + tid];
    if (tid == 0) s_shift = 0.0f;
    __syncthreads();

    // ---- heavy pass: stream future = hidden[b, start:start+H, :] once ----
    // warp w handles rows h = w, w+8, ... ; lane handles d4 = i*32+lane (float4)
    float4 a4[8];
    #pragma unroll
    for (int i = 0; i < 8; i++)
        a4[i] = reinterpret_cast<const float4*>(s_anchor)[i * 32 + lane];

    float msum[32];
    #pragma unroll
    for (int i = 0; i < 32; i++) msum[i] = 0.0f;
    float shift_acc = 0.0f;

    for (int h = warp; h < H_; h += 8) {
        const float4* row = reinterpret_cast<const float4*>(
            hidden + ((size_t)(b * T_ + start + h)) * D_);
        float ss = 0.0f;
        #pragma unroll
        for (int i = 0; i < 8; i++) {
            float4 f = row[i * 32 + lane];
            msum[4*i+0] += f.x; msum[4*i+1] += f.y;
            msum[4*i+2] += f.z; msum[4*i+3] += f.w;
            float dx = f.x - a4[i].x, dy = f.y - a4[i].y;
            float dz = f.z - a4[i].z, dw = f.w - a4[i].w;
            ss += dx*dx + dy*dy + dz*dz + dw*dw;
        }
        #pragma unroll
        for (int o = 16; o > 0; o >>= 1)
            ss += __shfl_xor_sync(0xffffffffu, ss, o);
        if (lane == 0) shift_acc += sqrtf(ss);
    }
    if (lane == 0) atomicAdd(&s_shift, shift_acc);

    #pragma unroll
    for (int i = 0; i < 8; i++) {
        int d = (i * 32 + lane) * 4;
        atomicAdd(&s_meanf[d + 0], msum[4*i+0]);
        atomicAdd(&s_meanf[d + 1], msum[4*i+1]);
        atomicAdd(&s_meanf[d + 2], msum[4*i+2]);
        atomicAdd(&s_meanf[d + 3], msum[4*i+3]);
    }
    __syncthreads();

    // ---- cosine similarity ----
    float dot = 0.0f, nf2 = 0.0f, na2 = 0.0f;
    const float invH = 1.0f / (float)H_;
    for (int i = tid; i < D_; i += NT) {
        float m = s_meanf[i] * invH;
        float av = s_anchor[i];
        dot += m * av;
        nf2 += m * m;
        na2 += av * av;
    }
    dot = blockReduceSum(dot, s_red, tid);
    nf2 = blockReduceSum(nf2, s_red, tid);
    na2 = blockReduceSum(na2, s_red, tid);

    const float eps = 1e-8f;
    float nr = fmaxf(sqrtf(na2), eps);
    float nf = fmaxf(sqrtf(nf2), eps);
    float sim = dot / (nr * nf);
    float hidden_c = fmaxf(0.0f, (1.0f - sim) * 0.5f);

    // ---- token_c ----
    const int anchor_tok = s_span[S_ - 1];  // span ends exactly at anchor_end
    float teq = (s_ftok[tid] == anchor_tok) ? 1.0f : 0.0f;
    teq = blockReduceSum(teq, s_red, tid);
    float token_c = 1.0f - teq * invH;

    // ---- span analysis (single thread; trivial) ----
    if (tid == 0) {
        int ffmask = 0, denom = 0;
        #pragma unroll
        for (int s = 0; s < S_; s++) {
            bool first = true;
            for (int j = 0; j < s; j++)
                if (s_span[j] == s_span[s]) { first = false; break; }
            if (first) { ffmask |= (1 << s); denom++; }
        }
        int first_root = -1;
        #pragma unroll
        for (int s = 0; s < S_; s++) {
            int al = s_alias[s_span[s]];
            if (al >= 0) { first_root = al; break; }
        }
        int root;
        if (first_root >= 0) {
            root = first_root;
        } else {
            int counts[S_], maxc = 0;
            #pragma unroll
            for (int s = 0; s < S_; s++) {
                int c = 0;
                for (int j = 0; j < S_; j++) c += (s_span[j] == s_span[s]);
                counts[s] = c;
                maxc = max(maxc, c);
            }
            int mode = 64;
            #pragma unroll
            for (int s = 0; s < S_; s++)
                if (counts[s] == maxc) mode = min(mode, s_span[s]);
            root = mode;
        }
        s_root = root;
        s_has = (compat_mask_of(root) != 0ull) ? 1 : 0;
        s_ffmask = ffmask;
        s_invdenom = 1.0f / (float)denom;
    }
    __syncthreads();

    // ---- per-window metrics: thread t handles window t (t < 241) ----
    const int root = s_root;
    const int has = s_has;
    const int ffmask = s_ffmask;
    const float invdenom = s_invdenom;
    const unsigned long long cmask = compat_mask_of(root);

    float sims = 0.0f, rp = 0.0f, regime = 0.0f, hit06 = 0.0f, best_v = -1e30f;
    if (tid < W_) {
        float ex = 0.0f, pos = 0.0f, ac = 0.0f, hd = 0.0f;
        unsigned long long wmask = 0ull;
        #pragma unroll
        for (int s = 0; s < S_; s++) {
            int tok = s_ftok[tid + s];
            wmask |= (1ull << tok);
            float eq = (tok == s_span[s]) ? 1.0f : 0.0f;
            ex  += eq;
            pos += eq * ((1.0f - 0.04f * (float)s) * (1.0f / 11.2f));
            rp  += (tok == root) ? 1.0f : 0.0f;
            ac  += (s_alias[tok] == root) ? 1.0f : 0.0f;
            hd  += (float)((cmask >> tok) & 1ull);
        }
        float ov = 0.0f;
        #pragma unroll
        for (int s = 0; s < S_; s++) {
            if (((ffmask >> s) & 1) && ((wmask >> s_span[s]) & 1ull)) ov += 1.0f;
        }
        ov *= invdenom;
        const float inv16 = 1.0f / 16.0f;
        ex *= inv16; rp *= inv16; ac *= inv16; hd *= inv16;

        regime = has ? (0.55f*hd + 0.2f*ov + 0.15f*ac + 0.1f*rp)
                     : (0.45f*ex + 0.3f*ov + 0.1f*ac + 0.15f*rp);
        sims = 0.25f*ex + 0.15f*ov + 0.35f*pos + 0.25f*regime;
        best_v = sims;
        hit06 = (sims >= 0.6f) ? 1.0f : 0.0f;
    }

    float best      = blockReduceMax(best_v, s_red, tid);
    float sum_sims  = blockReduceSum(sims,   s_red, tid);
    float sum_rp    = blockReduceSum(rp * (tid < W_ ? (1.0f/16.0f) : 0.0f), s_red, tid);
    float sum_reg   = blockReduceSum(regime, s_red, tid);
    float cnt06     = blockReduceSum(hit06,  s_red, tid);

    if (tid == 0) {
        const float invW = 1.0f / (float)W_;
        float mrp = sum_rp  * invW;
        float mrc = sum_reg * invW;
        float mean_sims = sum_sims * invW;
        float dmass = cnt06 * invW;
        float dcoh = 0.6f*mean_sims + 0.25f*mrp + 0.15f*mrc;
        float pattern_c = 1.0f - (0.6f*best + 0.2f*mrp + 0.2f*mrc);
        float contr = 0.2f*hidden_c + 0.2f*token_c + 0.6f*pattern_c;
        contr = fminf(fmaxf(contr, 0.0f), 1.0f);
        float future_shift = s_shift * invH;

        out[0 * NPAIR + pair] = contr;
        out[1 * NPAIR + pair] = future_shift;
        out[2 * NPAIR + pair] = sim;
        out[3 * NPAIR + pair] = hidden_c;
        out[4 * NPAIR + pair] = token_c;
        out[5 * NPAIR + pair] = pattern_c;
        out[6 * NPAIR + pair] = dmass;
        out[7 * NPAIR + pair] = dcoh;
    }
}

extern "C" void kernel_launch(void* const* d_in, const int* in_sizes, int n_in,
                              void* d_out, int out_size) {
    const float* hidden      = (const float*)d_in[0];
    const float* anchor_repr = (const float*)d_in[1];
    const int*   input_ids   = (const int*)d_in[2];
    const int*   anchor_end  = (const int*)d_in[3];
    float*       out         = (float*)d_out;
    cm_kernel<<<NPAIR, NT>>>(hidden, anchor_repr, input_ids, anchor_end, out);
}